// round 7
// baseline (speedup 1.0000x reference)
#include <cuda_runtime.h>
#include <cstdint>

#define N_NODES 100000
#define N_EDGES_MAX 800000
#define F_IN 256
#define N_HID 128
#define N_CLS 40

// ---------------- device scratch (static, no allocations) ----------------
__device__ float g_norm_src[N_NODES];
__device__ float g_norm_dst[N_NODES];
__device__ float g_h[(size_t)N_NODES * N_HID];    // layer-1 projected features
__device__ float g_act[(size_t)N_NODES * N_HID];  // layer-1 activations
__device__ float g_h2[(size_t)N_NODES * N_CLS];   // layer-2 projected features
__device__ uint32_t g_w1t[(size_t)N_HID * F_IN];  // W1^T [n][k], tf32-rna bits
__device__ uint32_t g_w2t[(size_t)N_CLS * N_HID]; // W2^T [n][k], tf32-rna bits
__device__ int g_indeg[N_NODES];
__device__ int g_outdeg[N_NODES];
__device__ int g_rowptr[N_NODES + 1];
__device__ int g_cursor[N_NODES];
__device__ int g_esrc[N_EDGES_MAX];
__device__ int g_idx64;

// ---------------- helpers ----------------
__device__ __forceinline__ int load_idx(const int* p, int e) {
    return g_idx64 ? p[2 * e] : p[e];
}
__device__ __forceinline__ uint32_t cvt_tf32(float f) {
    uint32_t u;
    asm("cvt.rna.tf32.f32 %0, %1;" : "=r"(u) : "f"(f));
    return u;
}
__device__ __forceinline__ void mma_tf32(float* c, const uint32_t* a, const uint32_t* b) {
    asm volatile("mma.sync.aligned.m16n8k8.row.col.f32.tf32.tf32.f32 "
        "{%0,%1,%2,%3}, {%4,%5,%6,%7}, {%8,%9}, {%0,%1,%2,%3};"
        : "+f"(c[0]), "+f"(c[1]), "+f"(c[2]), "+f"(c[3])
        : "r"(a[0]), "r"(a[1]), "r"(a[2]), "r"(a[3]), "r"(b[0]), "r"(b[1]));
}
__device__ __forceinline__ uint32_t smem_u32(const void* p) {
    return (uint32_t)__cvta_generic_to_shared(p);
}
__device__ __forceinline__ void cp16(uint32_t dst, const void* src, int sz) {
    asm volatile("cp.async.cg.shared.global [%0], [%1], 16, %2;" :: "r"(dst), "l"(src), "r"(sz) : "memory");
}
#define CP_COMMIT() asm volatile("cp.async.commit_group;" ::: "memory")
#define CP_WAIT(N)  asm volatile("cp.async.wait_group %0;" :: "n"(N) : "memory")

// ---------------- prep: zero degrees, detect idx dtype, transpose W1/W2 ----------------
__global__ void prep_kernel(const int* __restrict__ src32, const float* __restrict__ W1,
                            const float* __restrict__ W2, int n) {
    int i = blockIdx.x * blockDim.x + threadIdx.x;
    if (i == 0) {
        int is64 = 1;
        #pragma unroll 1
        for (int k = 0; k < 64; k++) {
            if (src32[2 * k + 1] != 0) { is64 = 0; break; }
        }
        g_idx64 = is64;
    }
    if (i < n) { g_indeg[i] = 0; g_outdeg[i] = 0; }
    if (i < N_HID * F_IN) {
        int nrow = i >> 8;          // 0..127
        int k = i & 255;            // 0..255
        g_w1t[(size_t)nrow * F_IN + k] = cvt_tf32(W1[(size_t)k * N_HID + nrow]);
    }
    if (i < N_CLS * N_HID) {
        int nrow = i >> 7;          // 0..39
        int k = i & 127;            // 0..127
        g_w2t[(size_t)nrow * N_HID + k] = cvt_tf32(W2[(size_t)k * N_CLS + nrow]);
    }
}

// ---------------- hist: degree counts ----------------
__global__ void hist_kernel(const int* __restrict__ src, const int* __restrict__ dst, int E) {
    int i = blockIdx.x * blockDim.x + threadIdx.x;
    if (i < E) {
        atomicAdd(&g_outdeg[load_idx(src, i)], 1);
        atomicAdd(&g_indeg[load_idx(dst, i)], 1);
    }
}

// ---------------- scan: prefix sum of indeg -> rowptr/cursor, plus norms ----------------
__global__ void scan_kernel(int n, int E) {
    __shared__ int wsum[32];
    __shared__ int stotal;
    int t = threadIdx.x;
    int lane = t & 31, w = t >> 5;
    int run = 0;
    for (int base = 0; base < n; base += 1024) {
        int i = base + t;
        int x = (i < n) ? g_indeg[i] : 0;
        int v = x;
        #pragma unroll
        for (int o = 1; o < 32; o <<= 1) {
            int y = __shfl_up_sync(0xFFFFFFFFu, v, o);
            if (lane >= o) v += y;
        }
        if (lane == 31) wsum[w] = v;
        __syncthreads();
        if (w == 0) {
            int s = wsum[lane];
            #pragma unroll
            for (int o = 1; o < 32; o <<= 1) {
                int y = __shfl_up_sync(0xFFFFFFFFu, s, o);
                if (lane >= o) s += y;
            }
            wsum[lane] = s;
            if (lane == 31) stotal = s;
        }
        __syncthreads();
        int excl = v - x + (w > 0 ? wsum[w - 1] : 0) + run;
        if (i < n) {
            g_rowptr[i] = excl;
            g_cursor[i] = excl;
            int od = g_outdeg[i];
            g_norm_src[i] = (od > 0) ? rsqrtf((float)od) : 0.f;
            g_norm_dst[i] = (x > 0) ? rsqrtf((float)x) : 0.f;
        }
        run += stotal;
        __syncthreads();
    }
    if (t == 0) g_rowptr[n] = E;
}

// ---------------- scatter: fill CSR edge-source list ----------------
__global__ void scatter_kernel(const int* __restrict__ src, const int* __restrict__ dst, int E) {
    int i = blockIdx.x * blockDim.x + threadIdx.x;
    if (i < E) {
        int s = load_idx(src, i);
        int d = load_idx(dst, i);
        int pos = atomicAdd(&g_cursor[d], 1);
        g_esrc[pos] = s;
    }
}

// ---------------- GEMM1 (mma tf32, cp.async pipelined): g_h = ns * (X @ W1) ----------------
// CTA 128x128, BK=32, K=256 -> 8 chunks, double-buffered.
// A is raw f32 bits (HW tf32 truncation); B pre-rounded rna.
#define G1_AS (128 * 36)           // words per tile (padded stride 36)
__global__ __launch_bounds__(256) void gemm1_mma_kernel(const float* __restrict__ X, int n) {
    extern __shared__ uint32_t sm1[];  // [buf0 A | buf0 B | buf1 A | buf1 B]
    int t = threadIdx.x;
    int wid = t >> 5;
    int lane = t & 31;
    int row0 = blockIdx.x * 128;

    int wr = wid & 1;
    int wc = wid >> 1;

    int lr = t >> 1;                 // 0..127
    int off = (t & 1) << 4;          // 0 or 16 (floats)
    int arow = row0 + lr;
    bool avalid = arow < n;
    int asz = avalid ? 16 : 0;
    const float* Xrow = X + (size_t)(avalid ? arow : 0) * F_IN;
    const uint32_t* Brow = g_w1t + (size_t)lr * F_IN;

    uint32_t sbase = smem_u32(sm1);
    uint32_t dstA = sbase + (uint32_t)(lr * 36 + off) * 4;
    uint32_t dstB = dstA + G1_AS * 4;

    float acc[4][4][4];
    #pragma unroll
    for (int f = 0; f < 4; f++)
        #pragma unroll
        for (int g = 0; g < 4; g++)
            #pragma unroll
            for (int q = 0; q < 4; q++) acc[f][g][q] = 0.f;

    int lg = lane >> 2;
    int lk = lane & 3;

    auto stage = [&](int kc, int b) {
        uint32_t boff = (uint32_t)b * (2 * G1_AS * 4);
        #pragma unroll
        for (int i = 0; i < 4; i++)
            cp16(dstA + boff + i * 16, Xrow + kc * 32 + off + i * 4, asz);
        #pragma unroll
        for (int i = 0; i < 4; i++)
            cp16(dstB + boff + i * 16, Brow + kc * 32 + off + i * 4, 16);
        CP_COMMIT();
    };

    stage(0, 0);
    #pragma unroll 1
    for (int kc = 0; kc < 8; kc++) {
        int b = kc & 1;
        if (kc < 7) { stage(kc + 1, b ^ 1); CP_WAIT(1); }
        else CP_WAIT(0);
        __syncthreads();

        const uint32_t* As = sm1 + b * (2 * G1_AS);
        const uint32_t* Bs = As + G1_AS;

        #pragma unroll
        for (int k8 = 0; k8 < 4; k8++) {
            int kb = k8 * 8;
            uint32_t a[4][4], bfr[4][2];
            #pragma unroll
            for (int f = 0; f < 4; f++) {
                int r = wr * 64 + f * 16 + lg;
                a[f][0] = As[r * 36 + kb + lk];
                a[f][1] = As[(r + 8) * 36 + kb + lk];
                a[f][2] = As[r * 36 + kb + lk + 4];
                a[f][3] = As[(r + 8) * 36 + kb + lk + 4];
            }
            #pragma unroll
            for (int g = 0; g < 4; g++) {
                int ccol = wc * 32 + g * 8 + lg;
                bfr[g][0] = Bs[ccol * 36 + kb + lk];
                bfr[g][1] = Bs[ccol * 36 + kb + lk + 4];
            }
            #pragma unroll
            for (int f = 0; f < 4; f++)
                #pragma unroll
                for (int g = 0; g < 4; g++)
                    mma_tf32(acc[f][g], a[f], bfr[g]);
        }
        __syncthreads();
    }

    #pragma unroll
    for (int f = 0; f < 4; f++) {
        int rbase = row0 + wr * 64 + f * 16;
        int r0 = rbase + lg;
        int r1 = r0 + 8;
        float ns0 = (r0 < n) ? g_norm_src[r0] : 0.f;
        float ns1 = (r1 < n) ? g_norm_src[r1] : 0.f;
        #pragma unroll
        for (int g = 0; g < 4; g++) {
            int cc = wc * 32 + g * 8 + 2 * lk;
            if (r0 < n) {
                float2 o = make_float2(acc[f][g][0] * ns0, acc[f][g][1] * ns0);
                *(float2*)(g_h + (size_t)r0 * N_HID + cc) = o;
            }
            if (r1 < n) {
                float2 o = make_float2(acc[f][g][2] * ns1, acc[f][g][3] * ns1);
                *(float2*)(g_h + (size_t)r1 * N_HID + cc) = o;
            }
        }
    }
}

// ---------------- SpMM1 (CSR gather, ILP4) + activation fused ----------------
__global__ __launch_bounds__(256) void spmm1_csr_kernel(const float* __restrict__ b1, int n) {
    __shared__ float b1s[N_HID];
    int t = threadIdx.x;
    int w = t >> 5, lane = t & 31;
    if (t < N_HID) b1s[t] = b1[t];
    __syncthreads();

    int d = blockIdx.x * 8 + w;
    if (d >= n) return;

    int start = g_rowptr[d];
    int end = g_rowptr[d + 1];
    int c = lane << 2;

    float4 a0 = make_float4(0.f, 0.f, 0.f, 0.f);
    float4 a1 = make_float4(0.f, 0.f, 0.f, 0.f);
    float4 a2 = make_float4(0.f, 0.f, 0.f, 0.f);
    float4 a3 = make_float4(0.f, 0.f, 0.f, 0.f);

    for (int base = start; base < end; base += 32) {
        int m = end - base;
        if (m > 32) m = 32;
        int sv = (lane < m) ? g_esrc[base + lane] : 0;
        int i = 0;
        for (; i + 4 <= m; i += 4) {
            int s0 = __shfl_sync(0xFFFFFFFFu, sv, i);
            int s1 = __shfl_sync(0xFFFFFFFFu, sv, i + 1);
            int s2 = __shfl_sync(0xFFFFFFFFu, sv, i + 2);
            int s3 = __shfl_sync(0xFFFFFFFFu, sv, i + 3);
            float4 v0 = *(const float4*)(g_h + (size_t)s0 * N_HID + c);
            float4 v1 = *(const float4*)(g_h + (size_t)s1 * N_HID + c);
            float4 v2 = *(const float4*)(g_h + (size_t)s2 * N_HID + c);
            float4 v3 = *(const float4*)(g_h + (size_t)s3 * N_HID + c);
            a0.x += v0.x; a0.y += v0.y; a0.z += v0.z; a0.w += v0.w;
            a1.x += v1.x; a1.y += v1.y; a1.z += v1.z; a1.w += v1.w;
            a2.x += v2.x; a2.y += v2.y; a2.z += v2.z; a2.w += v2.w;
            a3.x += v3.x; a3.y += v3.y; a3.z += v3.z; a3.w += v3.w;
        }
        for (; i < m; i++) {
            int s0 = __shfl_sync(0xFFFFFFFFu, sv, i);
            float4 v0 = *(const float4*)(g_h + (size_t)s0 * N_HID + c);
            a0.x += v0.x; a0.y += v0.y; a0.z += v0.z; a0.w += v0.w;
        }
    }
    a0.x += a1.x + a2.x + a3.x;
    a0.y += a1.y + a2.y + a3.y;
    a0.z += a1.z + a2.z + a3.z;
    a0.w += a1.w + a2.w + a3.w;

    float nd = g_norm_dst[d];
    float ns = g_norm_src[d];
    float4 bb = *(const float4*)(b1s + c);
    float4 o;
    o.x = fmaxf(fmaf(a0.x, nd, bb.x), 0.f) * ns;
    o.y = fmaxf(fmaf(a0.y, nd, bb.y), 0.f) * ns;
    o.z = fmaxf(fmaf(a0.z, nd, bb.z), 0.f) * ns;
    o.w = fmaxf(fmaf(a0.w, nd, bb.w), 0.f) * ns;
    *(float4*)(g_act + (size_t)d * N_HID + c) = o;
}

// ---------------- GEMM2 (mma tf32): g_h2[n,40] = g_act @ W2 ----------------
// CTA 256 rows x 40 cols, K=128 in 4 chunks of 32, A double-buffered cp.async,
// B (W2^T, pre-rounded) loaded once. 8 warps: warp w owns rows w*32..+31.
#define G2_AS (256 * 36)            // words per A tile
#define G2_BOFF (2 * G2_AS)         // B offset in words
__global__ __launch_bounds__(256) void gemm2_mma_kernel(int n) {
    extern __shared__ uint32_t sm2[];  // [A buf0 | A buf1 | B(40x132)]
    int t = threadIdx.x;
    int wid = t >> 5;
    int lane = t & 31;
    int row0 = blockIdx.x * 256;

    int lg = lane >> 2;
    int lk = lane & 3;

    // B: 40 rows x 128 cols -> smem stride 132
    for (int idx = t; idx < 40 * 32; idx += 256) {
        int rw = idx >> 5;
        int c4 = (idx & 31) << 2;
        uint4 u = *(const uint4*)(g_w2t + (size_t)rw * N_HID + c4);
        *(uint4*)(sm2 + G2_BOFF + rw * 132 + c4) = u;
    }

    int arow = row0 + t;
    bool avalid = arow < n;
    int asz = avalid ? 16 : 0;
    const float* Arow = g_act + (size_t)(avalid ? arow : 0) * N_HID;
    uint32_t dstA = smem_u32(sm2) + (uint32_t)(t * 36) * 4;

    auto stage = [&](int kc, int b) {
        uint32_t boff = (uint32_t)b * (G2_AS * 4);
        #pragma unroll
        for (int i = 0; i < 8; i++)
            cp16(dstA + boff + i * 16, Arow + kc * 32 + i * 4, asz);
        CP_COMMIT();
    };

    float acc[2][5][4];
    #pragma unroll
    for (int f = 0; f < 2; f++)
        #pragma unroll
        for (int g = 0; g < 5; g++)
            #pragma unroll
            for (int q = 0; q < 4; q++) acc[f][g][q] = 0.f;

    stage(0, 0);
    #pragma unroll 1
    for (int kc = 0; kc < 4; kc++) {
        int b = kc & 1;
        if (kc < 3) { stage(kc + 1, b ^ 1); CP_WAIT(1); }
        else CP_WAIT(0);
        __syncthreads();

        const uint32_t* As = sm2 + b * G2_AS;
        const uint32_t* Bs = sm2 + G2_BOFF;

        #pragma unroll
        for (int k8 = 0; k8 < 4; k8++) {
            int kb = k8 * 8;
            int kgl = kc * 32 + kb;
            uint32_t a[2][4], bfr[5][2];
            #pragma unroll
            for (int f = 0; f < 2; f++) {
                int r = wid * 32 + f * 16 + lg;
                a[f][0] = As[r * 36 + kb + lk];
                a[f][1] = As[(r + 8) * 36 + kb + lk];
                a[f][2] = As[r * 36 + kb + lk + 4];
                a[f][3] = As[(r + 8) * 36 + kb + lk + 4];
            }
            #pragma unroll
            for (int g = 0; g < 5; g++) {
                int ccol = g * 8 + lg;
                bfr[g][0] = Bs[ccol * 132 + kgl + lk];
                bfr[g][1] = Bs[ccol * 132 + kgl + lk + 4];
            }
            #pragma unroll
            for (int f = 0; f < 2; f++)
                #pragma unroll
                for (int g = 0; g < 5; g++)
                    mma_tf32(acc[f][g], a[f], bfr[g]);
        }
        __syncthreads();
    }

    #pragma unroll
    for (int f = 0; f < 2; f++) {
        int r0 = row0 + wid * 32 + f * 16 + lg;
        int r1 = r0 + 8;
        #pragma unroll
        for (int g = 0; g < 5; g++) {
            int cc = g * 8 + 2 * lk;
            if (r0 < n)
                *(float2*)(g_h2 + (size_t)r0 * N_CLS + cc) = make_float2(acc[f][g][0], acc[f][g][1]);
            if (r1 < n)
                *(float2*)(g_h2 + (size_t)r1 * N_CLS + cc) = make_float2(acc[f][g][2], acc[f][g][3]);
        }
    }
}

// ---------------- SpMM2 (CSR gather, ILP4) + finalize fused ----------------
__global__ __launch_bounds__(256) void spmm2_csr_kernel(const float* __restrict__ b2,
                                                        float* __restrict__ out, int n) {
    __shared__ float b2s[N_CLS];
    int t = threadIdx.x;
    int w = t >> 5, lane = t & 31;
    if (t < N_CLS) b2s[t] = b2[t];
    __syncthreads();

    int d = blockIdx.x * 8 + w;
    if (d >= n) return;

    int start = g_rowptr[d];
    int end = g_rowptr[d + 1];

    float p0 = 0.f, p1 = 0.f, p2 = 0.f, p3 = 0.f;   // col = lane
    float q0 = 0.f, q1 = 0.f, q2 = 0.f, q3 = 0.f;   // col = 32+lane (lane<8)
    bool hi = lane < 8;

    for (int base = start; base < end; base += 32) {
        int m = end - base;
        if (m > 32) m = 32;
        int sv = (lane < m) ? g_esrc[base + lane] : 0;
        int i = 0;
        for (; i + 4 <= m; i += 4) {
            int s0 = __shfl_sync(0xFFFFFFFFu, sv, i);
            int s1 = __shfl_sync(0xFFFFFFFFu, sv, i + 1);
            int s2 = __shfl_sync(0xFFFFFFFFu, sv, i + 2);
            int s3 = __shfl_sync(0xFFFFFFFFu, sv, i + 3);
            const float* h0 = g_h2 + (size_t)s0 * N_CLS;
            const float* h1 = g_h2 + (size_t)s1 * N_CLS;
            const float* h2p = g_h2 + (size_t)s2 * N_CLS;
            const float* h3 = g_h2 + (size_t)s3 * N_CLS;
            p0 += h0[lane]; p1 += h1[lane]; p2 += h2p[lane]; p3 += h3[lane];
            if (hi) { q0 += h0[32 + lane]; q1 += h1[32 + lane]; q2 += h2p[32 + lane]; q3 += h3[32 + lane]; }
        }
        for (; i < m; i++) {
            int s0 = __shfl_sync(0xFFFFFFFFu, sv, i);
            const float* h0 = g_h2 + (size_t)s0 * N_CLS;
            p0 += h0[lane];
            if (hi) q0 += h0[32 + lane];
        }
    }
    p0 += p1 + p2 + p3;
    q0 += q1 + q2 + q3;

    float nd = g_norm_dst[d];
    float* op = out + (size_t)d * N_CLS;
    op[lane] = fmaf(p0, nd, b2s[lane]);
    if (hi) op[32 + lane] = fmaf(q0, nd, b2s[32 + lane]);
}

// ---------------- launch ----------------
extern "C" void kernel_launch(void* const* d_in, const int* in_sizes, int n_in,
                              void* d_out, int out_size) {
    const float* X  = (const float*)d_in[0];
    const int* src  = (const int*)d_in[1];
    const int* dst  = (const int*)d_in[2];
    const float* W1 = (const float*)d_in[3];
    const float* b1 = (const float*)d_in[4];
    const float* W2 = (const float*)d_in[5];
    const float* b2 = (const float*)d_in[6];
    float* out = (float*)d_out;

    int n = in_sizes[0] / F_IN;   // 100000
    int E = in_sizes[1];          // 800000

    const int g1_smem = 4 * G1_AS * 4;                 // 73728 B
    const int g2_smem = (2 * G2_AS + 40 * 132) * 4;    // 94848 B
    cudaFuncSetAttribute(gemm1_mma_kernel, cudaFuncAttributeMaxDynamicSharedMemorySize, g1_smem);
    cudaFuncSetAttribute(gemm2_mma_kernel, cudaFuncAttributeMaxDynamicSharedMemorySize, g2_smem);

    prep_kernel<<<(n + 255) / 256, 256>>>(src, W1, W2, n);
    hist_kernel<<<(E + 255) / 256, 256>>>(src, dst, E);
    scan_kernel<<<1, 1024>>>(n, E);
    scatter_kernel<<<(E + 255) / 256, 256>>>(src, dst, E);
    gemm1_mma_kernel<<<(n + 127) / 128, 256, g1_smem>>>(X, n);
    spmm1_csr_kernel<<<(n + 7) / 8, 256>>>(b1, n);
    gemm2_mma_kernel<<<(n + 255) / 256, 256, g2_smem>>>(n);
    spmm2_csr_kernel<<<(n + 7) / 8, 256>>>(b2, out, n);
}